// round 1
// baseline (speedup 1.0000x reference)
#include <cuda_runtime.h>
#include <mma.h>
#include <cstdint>

using namespace nvcuda;

// Problem constants (fixed by the dataset)
#define kE    2048
#define kHQ   16
#define kHK   4
#define kD    128
#define kG    4
#define kKVE  512
#define kB    2
#define kN    2048
#define kROWS (kB * kN)   // 4096 token rows

// ---------------------------------------------------------------------------
// Scratch (device globals — allocation-free per harness rules)
// ---------------------------------------------------------------------------
__device__ float g_Q[kB * kHQ * kN * kD];    // [b][hq][n][d], pre-scaled by 1/sqrt(D)
__device__ float g_K[kB * kHK * kN * kD];    // [b][hk][n][d]
__device__ float g_V[kB * kHK * kN * kD];    // [b][hk][n][d]
__device__ float g_Ctx[kB * kN * kE];        // [b*n][hq*D + d]

// ---------------------------------------------------------------------------
// Generic GEMM: C(M,N) = A(M,K) @ W(N,K)^T + bias,  tf32 WMMA, 128x128x32 tiles
// mode 0: plain row-major out[m*N + n]
// mode 1: Q scatter  -> g_Q[((b*HQ+h)*kN + nseq)*kD + d], scaled by 1/sqrt(D)
// mode 2: KV scatter -> g_K/V[((b*HK+h)*kN + nseq)*kD + d]
// ---------------------------------------------------------------------------
__global__ __launch_bounds__(256) void gemm_xwt(
    const float* __restrict__ A, const float* __restrict__ W,
    const float* __restrict__ bias, float* __restrict__ Cout,
    int M, int N, int K, int mode)
{
    constexpr int BK = 32;
    __shared__ float shA[128][36];   // [m][k], pad 4 (ld multiple of 4, float4-aligned)
    __shared__ float shB[128][36];   // [n][k]

    const int tid = threadIdx.x;
    const int m0 = blockIdx.y * 128;
    const int n0 = blockIdx.x * 128;
    const int w  = tid >> 5;
    const int wm = (w & 3) * 32;   // warp row offset (2 frags of 16)
    const int wn = (w >> 2) * 64;  // warp col offset (4 frags of 16)

    wmma::fragment<wmma::accumulator, 16, 16, 8, float> acc[2][4];
    // bias broadcast init: ld=0 replicates the 16-col bias row across all 16 rows
    #pragma unroll
    for (int i = 0; i < 2; ++i)
        #pragma unroll
        for (int j = 0; j < 4; ++j)
            wmma::load_matrix_sync(acc[i][j], bias + n0 + wn + j * 16, 0, wmma::mem_row_major);

    for (int k0 = 0; k0 < K; k0 += BK) {
        __syncthreads();
        #pragma unroll
        for (int i = 0; i < 4; ++i) {
            int f  = tid + i * 256;          // float4 index, 1024 total per tile
            int r  = f >> 3;
            int c4 = (f & 7) * 4;
            *(float4*)&shA[r][c4] = *(const float4*)(A + (size_t)(m0 + r) * K + k0 + c4);
            *(float4*)&shB[r][c4] = *(const float4*)(W + (size_t)(n0 + r) * K + k0 + c4);
        }
        __syncthreads();

        #pragma unroll
        for (int kk = 0; kk < BK; kk += 8) {
            wmma::fragment<wmma::matrix_a, 16, 16, 8, wmma::precision::tf32, wmma::row_major> af[2];
            wmma::fragment<wmma::matrix_b, 16, 16, 8, wmma::precision::tf32, wmma::col_major> bf[4];
            #pragma unroll
            for (int i = 0; i < 2; ++i) {
                wmma::load_matrix_sync(af[i], &shA[wm + i * 16][kk], 36);
                #pragma unroll
                for (int t = 0; t < af[i].num_elements; ++t)
                    af[i].x[t] = wmma::__float_to_tf32(af[i].x[t]);
            }
            #pragma unroll
            for (int j = 0; j < 4; ++j) {
                wmma::load_matrix_sync(bf[j], &shB[wn + j * 16][kk], 36);
                #pragma unroll
                for (int t = 0; t < bf[j].num_elements; ++t)
                    bf[j].x[t] = wmma::__float_to_tf32(bf[j].x[t]);
            }
            #pragma unroll
            for (int i = 0; i < 2; ++i)
                #pragma unroll
                for (int j = 0; j < 4; ++j)
                    wmma::mma_sync(acc[i][j], af[i], bf[j], acc[i][j]);
        }
    }

    const float scale = (mode == 1) ? rsqrtf((float)kD) : 1.0f;
    #pragma unroll
    for (int i = 0; i < 2; ++i) {
        #pragma unroll
        for (int j = 0; j < 4; ++j) {
            if (mode == 1) {
                #pragma unroll
                for (int t = 0; t < acc[i][j].num_elements; ++t)
                    acc[i][j].x[t] *= scale;
            }
            const int mrow = m0 + wm + i * 16;
            const int ncol = n0 + wn + j * 16;
            float* dst;
            int ld;
            if (mode == 0) {
                dst = Cout + (size_t)mrow * N + ncol;
                ld  = N;
            } else {
                const int heads = (mode == 1) ? kHQ : kHK;
                const int b = mrow / kN, nseq = mrow % kN;
                const int h = ncol / kD, d = ncol % kD;
                dst = Cout + (((size_t)(b * heads + h) * kN + nseq) * kD + d);
                ld  = kD;
            }
            wmma::store_matrix_sync(dst, acc[i][j], ld, wmma::mem_row_major);
        }
    }
}

// ---------------------------------------------------------------------------
// Flash attention (causal, GQA): 64-row Q tile per CTA, 64-col KV tiles.
// grid = (kN/64, kHQ, kB), 256 threads / 8 warps. tf32 WMMA for S and PV.
// ---------------------------------------------------------------------------
#define BR 64
#define BC 64
#define QLD 132   // 128 + 4 pad
#define SLD 68    // 64 + 4 pad

// floats: 4 tiles of 64*132 (Q,K,V,O) + S 64*68 + m,l (64 each)
#define ATTN_SMEM_FLOATS (4 * BR * QLD + BR * SLD + 2 * BR)
#define ATTN_SMEM_BYTES  (ATTN_SMEM_FLOATS * 4)

extern __shared__ float s_attn[];

__global__ __launch_bounds__(256) void attn_kernel(
    const float* __restrict__ Q, const float* __restrict__ K,
    const float* __restrict__ V, float* __restrict__ Ctx,
    const int* __restrict__ causal_flag)
{
    float* shQ = s_attn;
    float* shK = shQ + BR * QLD;
    float* shV = shK + BR * QLD;
    float* shO = shV + BR * QLD;
    float* shS = shO + BR * QLD;
    float* shm = shS + BR * SLD;
    float* shl = shm + BR;

    const int r   = blockIdx.x;       // query tile
    const int hq  = blockIdx.y;
    const int b   = blockIdx.z;
    const int hk  = hq / kG;
    const int tid = threadIdx.x;
    const bool causal = (*causal_flag) != 0;

    const float* Qb = Q + (((size_t)(b * kHQ + hq) * kN) + (size_t)r * BR) * kD;
    const float* Kb = K + ((size_t)(b * kHK + hk) * kN) * kD;
    const float* Vb = V + ((size_t)(b * kHK + hk) * kN) * kD;

    // load Q tile (pre-scaled), init O / m / l
    #pragma unroll
    for (int i = 0; i < 8; ++i) {
        int f = tid + i * 256;                 // 2048 float4s
        int row = f >> 5, c4 = (f & 31) * 4;
        *(float4*)&shQ[row * QLD + c4] = *(const float4*)(Qb + (size_t)row * kD + c4);
    }
    for (int i = tid; i < BR * QLD; i += 256) shO[i] = 0.0f;
    if (tid < BR) { shm[tid] = -1e30f; shl[tid] = 0.0f; }

    const int ntiles = kN / BC;
    const int jmax = causal ? r : (ntiles - 1);
    const int w = tid >> 5;
    const int wr  = (w & 3) * 16;   // warp's 16 S/O rows
    const int wcS = (w >> 2) * 32;  // warp's 32 S cols
    const int wcO = (w >> 2) * 64;  // warp's 64 O cols

    for (int j = 0; j <= jmax; ++j) {
        __syncthreads();   // protect shK/shV/shS reuse from previous iter
        #pragma unroll
        for (int i = 0; i < 8; ++i) {
            int f = tid + i * 256;
            int row = f >> 5, c4 = (f & 31) * 4;
            *(float4*)&shK[row * QLD + c4] =
                *(const float4*)(Kb + ((size_t)(j * BC + row)) * kD + c4);
            *(float4*)&shV[row * QLD + c4] =
                *(const float4*)(Vb + ((size_t)(j * BC + row)) * kD + c4);
        }
        __syncthreads();

        // ---- S = Q @ K^T (64x64, K-dim 128) ----
        {
            wmma::fragment<wmma::accumulator, 16, 16, 8, float> sacc[2];
            #pragma unroll
            for (int jj = 0; jj < 2; ++jj) wmma::fill_fragment(sacc[jj], 0.0f);
            #pragma unroll
            for (int kk = 0; kk < kD; kk += 8) {
                wmma::fragment<wmma::matrix_a, 16, 16, 8, wmma::precision::tf32, wmma::row_major> af;
                wmma::load_matrix_sync(af, &shQ[wr * QLD + kk], QLD);
                #pragma unroll
                for (int t = 0; t < af.num_elements; ++t) af.x[t] = wmma::__float_to_tf32(af.x[t]);
                #pragma unroll
                for (int jj = 0; jj < 2; ++jj) {
                    wmma::fragment<wmma::matrix_b, 16, 16, 8, wmma::precision::tf32, wmma::col_major> bf;
                    wmma::load_matrix_sync(bf, &shK[(wcS + jj * 16) * QLD + kk], QLD);
                    #pragma unroll
                    for (int t = 0; t < bf.num_elements; ++t) bf.x[t] = wmma::__float_to_tf32(bf.x[t]);
                    wmma::mma_sync(sacc[jj], af, bf, sacc[jj]);
                }
            }
            #pragma unroll
            for (int jj = 0; jj < 2; ++jj)
                wmma::store_matrix_sync(&shS[wr * SLD + wcS + jj * 16], sacc[jj], SLD,
                                        wmma::mem_row_major);
        }
        __syncthreads();

        // ---- online softmax: 4 threads per row ----
        {
            const int row = tid >> 2;
            const int l4  = tid & 3;
            const bool diag = causal && (j == r);
            const int qpos = r * BR + row;
            float sv[16];
            float mloc = -1e30f;
            #pragma unroll
            for (int c = 0; c < 16; ++c) {
                int col = l4 * 16 + c;
                float s = shS[row * SLD + col];
                if (diag && (j * BC + col) > qpos) s = -1e30f;
                sv[c] = s;
                mloc = fmaxf(mloc, s);
            }
            #pragma unroll
            for (int o = 1; o < 4; o <<= 1)
                mloc = fmaxf(mloc, __shfl_xor_sync(0xffffffffu, mloc, o));
            const float mold = shm[row];
            const float mnew = fmaxf(mold, mloc);
            const float alpha = __expf(mold - mnew);
            float lsum = 0.0f;
            #pragma unroll
            for (int c = 0; c < 16; ++c) {
                float p = __expf(sv[c] - mnew);
                shS[row * SLD + l4 * 16 + c] = p;
                lsum += p;
            }
            #pragma unroll
            for (int o = 1; o < 4; o <<= 1)
                lsum += __shfl_xor_sync(0xffffffffu, lsum, o);
            if (l4 == 0) { shm[row] = mnew; shl[row] = alpha * shl[row] + lsum; }
            // rescale O row by alpha (this row is owned exclusively by these 4 lanes)
            for (int c = l4; c < kD; c += 4) shO[row * QLD + c] *= alpha;
        }
        __syncthreads();

        // ---- O += P @ V (64x128, K-dim 64) ----
        {
            wmma::fragment<wmma::accumulator, 16, 16, 8, float> oacc[4];
            #pragma unroll
            for (int ff = 0; ff < 4; ++ff)
                wmma::load_matrix_sync(oacc[ff], &shO[wr * QLD + wcO + ff * 16], QLD,
                                       wmma::mem_row_major);
            #pragma unroll
            for (int kk = 0; kk < BC; kk += 8) {
                wmma::fragment<wmma::matrix_a, 16, 16, 8, wmma::precision::tf32, wmma::row_major> af;
                wmma::load_matrix_sync(af, &shS[wr * SLD + kk], SLD);
                #pragma unroll
                for (int t = 0; t < af.num_elements; ++t) af.x[t] = wmma::__float_to_tf32(af.x[t]);
                #pragma unroll
                for (int ff = 0; ff < 4; ++ff) {
                    wmma::fragment<wmma::matrix_b, 16, 16, 8, wmma::precision::tf32, wmma::row_major> bf;
                    wmma::load_matrix_sync(bf, &shV[kk * QLD + wcO + ff * 16], QLD);
                    #pragma unroll
                    for (int t = 0; t < bf.num_elements; ++t) bf.x[t] = wmma::__float_to_tf32(bf.x[t]);
                    wmma::mma_sync(oacc[ff], af, bf, oacc[ff]);
                }
            }
            #pragma unroll
            for (int ff = 0; ff < 4; ++ff)
                wmma::store_matrix_sync(&shO[wr * QLD + wcO + ff * 16], oacc[ff], QLD,
                                        wmma::mem_row_major);
        }
    }
    __syncthreads();

    // epilogue: divide by l, write Ctx[(b*N + qrow)][hq*D + d]
    for (int i = tid; i < BR * kD; i += 256) {
        const int row = i >> 7, col = i & 127;
        const float inv = 1.0f / shl[row];
        Ctx[((size_t)b * kN + (size_t)r * BR + row) * kE + hq * kD + col] =
            shO[row * QLD + col] * inv;
    }
}

// ---------------------------------------------------------------------------
// Launch
// ---------------------------------------------------------------------------
extern "C" void kernel_launch(void* const* d_in, const int* in_sizes, int n_in,
                              void* d_out, int out_size)
{
    const float* query = (const float*)d_in[0];
    const float* key   = (const float*)d_in[1];
    const float* value = (const float*)d_in[2];
    const float* Wq    = (const float*)d_in[3];
    const float* bq    = (const float*)d_in[4];
    const float* Wk    = (const float*)d_in[5];
    const float* bk    = (const float*)d_in[6];
    const float* Wv    = (const float*)d_in[7];
    const float* bv    = (const float*)d_in[8];
    const float* Wo    = (const float*)d_in[9];
    const float* bo    = (const float*)d_in[10];
    const int* is_causal = (const int*)d_in[11];
    float* out = (float*)d_out;

    float *Qs, *Ks, *Vs, *Ctx;
    cudaGetSymbolAddress((void**)&Qs, g_Q);
    cudaGetSymbolAddress((void**)&Ks, g_K);
    cudaGetSymbolAddress((void**)&Vs, g_V);
    cudaGetSymbolAddress((void**)&Ctx, g_Ctx);

    cudaFuncSetAttribute(attn_kernel, cudaFuncAttributeMaxDynamicSharedMemorySize,
                         ATTN_SMEM_BYTES);

    dim3 thr(256);
    // Q projection (scatter + 1/sqrt(D))
    gemm_xwt<<<dim3(kE / 128, kROWS / 128), thr>>>(query, Wq, bq, Qs, kROWS, kE, kE, 1);
    // K, V projections (scatter)
    gemm_xwt<<<dim3(kKVE / 128, kROWS / 128), thr>>>(key, Wk, bk, Ks, kROWS, kKVE, kE, 2);
    gemm_xwt<<<dim3(kKVE / 128, kROWS / 128), thr>>>(value, Wv, bv, Vs, kROWS, kKVE, kE, 2);
    // attention
    attn_kernel<<<dim3(kN / BR, kHQ, kB), thr, ATTN_SMEM_BYTES>>>(Qs, Ks, Vs, Ctx, is_causal);
    // output projection
    gemm_xwt<<<dim3(kE / 128, kROWS / 128), thr>>>(Ctx, Wo, bo, out, kROWS, kE, kE, 0);
}

// round 2
// speedup vs baseline: 1.5251x; 1.5251x over previous
#include <cuda_runtime.h>
#include <cuda_pipeline.h>
#include <mma.h>
#include <cstdint>

using namespace nvcuda;

// Problem constants (fixed by the dataset)
#define kE    2048
#define kHQ   16
#define kHK   4
#define kD    128
#define kG    4
#define kKVE  512
#define kB    2
#define kN    2048
#define kROWS (kB * kN)   // 4096 token rows

// ---------------------------------------------------------------------------
// Scratch (device globals — allocation-free per harness rules)
// ---------------------------------------------------------------------------
__device__ float g_Q[kB * kHQ * kN * kD];    // [b][hq][n][d], pre-scaled by 1/sqrt(D)
__device__ float g_K[kB * kHK * kN * kD];    // [b][hk][n][d]
__device__ float g_V[kB * kHK * kN * kD];    // [b][hk][n][d]
__device__ float g_Ctx[kB * kN * kE];        // [b*n][hq*D + d]

extern __shared__ float dynsmem[];

__device__ __forceinline__ unsigned f2tf(float x) {
    unsigned r;
    asm("cvt.rna.tf32.f32 %0, %1;" : "=r"(r) : "f"(x));
    return r;
}

__device__ __forceinline__ void mma_tf32(float* c, const unsigned* a,
                                         unsigned b0, unsigned b1) {
    asm volatile(
        "mma.sync.aligned.m16n8k8.row.col.f32.tf32.tf32.f32 "
        "{%0,%1,%2,%3}, {%4,%5,%6,%7}, {%8,%9}, {%0,%1,%2,%3};"
        : "+f"(c[0]), "+f"(c[1]), "+f"(c[2]), "+f"(c[3])
        : "r"(a[0]), "r"(a[1]), "r"(a[2]), "r"(a[3]), "r"(b0), "r"(b1));
}

// ---------------------------------------------------------------------------
// GEMM: C(M,N) = A(M,K) @ W(N,K)^T + bias.  tf32 WMMA, 128x128x32 tiles,
// cp.async double-buffered.
// mode 0: plain row-major; mode 1: Q scatter (x 1/sqrt(D)); mode 2: KV scatter
// ---------------------------------------------------------------------------
__global__ __launch_bounds__(256) void gemm_xwt(
    const float* __restrict__ A, const float* __restrict__ W,
    const float* __restrict__ bias, float* __restrict__ Cout,
    int M, int N, int K, int mode)
{
    constexpr int BK = 32;
    constexpr int LD = 36;            // 32 + 4 pad
    constexpr int TILE = 128 * LD;
    float* shA = dynsmem;             // [2][TILE]
    float* shB = dynsmem + 2 * TILE;  // [2][TILE]

    const int tid = threadIdx.x;
    const int m0 = blockIdx.y * 128;
    const int n0 = blockIdx.x * 128;
    const int w  = tid >> 5;
    const int wm = (w & 3) * 32;
    const int wn = (w >> 2) * 64;

    wmma::fragment<wmma::accumulator, 16, 16, 8, float> acc[2][4];
    #pragma unroll
    for (int i = 0; i < 2; ++i)
        #pragma unroll
        for (int j = 0; j < 4; ++j)
            wmma::load_matrix_sync(acc[i][j], bias + n0 + wn + j * 16, 0, wmma::mem_row_major);

    auto stage = [&](int bufi, int k0) {
        #pragma unroll
        for (int i = 0; i < 4; ++i) {
            int f = tid + i * 256;
            int r = f >> 3, c4 = (f & 7) * 4;
            __pipeline_memcpy_async(&shA[bufi * TILE + r * LD + c4],
                                    A + (size_t)(m0 + r) * K + k0 + c4, 16);
            __pipeline_memcpy_async(&shB[bufi * TILE + r * LD + c4],
                                    W + (size_t)(n0 + r) * K + k0 + c4, 16);
        }
        __pipeline_commit();
    };

    stage(0, 0);
    int buf = 0;
    for (int k0 = 0; k0 < K; k0 += BK) {
        const bool more = (k0 + BK < K);
        if (more) stage(buf ^ 1, k0 + BK);
        __pipeline_wait_prior(more ? 1 : 0);
        __syncthreads();

        const float* sA = shA + buf * TILE;
        const float* sB = shB + buf * TILE;
        #pragma unroll
        for (int kk = 0; kk < BK; kk += 8) {
            wmma::fragment<wmma::matrix_a, 16, 16, 8, wmma::precision::tf32, wmma::row_major> af[2];
            wmma::fragment<wmma::matrix_b, 16, 16, 8, wmma::precision::tf32, wmma::col_major> bf[4];
            #pragma unroll
            for (int i = 0; i < 2; ++i) {
                wmma::load_matrix_sync(af[i], sA + (wm + i * 16) * LD + kk, LD);
                #pragma unroll
                for (int t = 0; t < af[i].num_elements; ++t)
                    af[i].x[t] = wmma::__float_to_tf32(af[i].x[t]);
            }
            #pragma unroll
            for (int j = 0; j < 4; ++j) {
                wmma::load_matrix_sync(bf[j], sB + (wn + j * 16) * LD + kk, LD);
                #pragma unroll
                for (int t = 0; t < bf[j].num_elements; ++t)
                    bf[j].x[t] = wmma::__float_to_tf32(bf[j].x[t]);
            }
            #pragma unroll
            for (int i = 0; i < 2; ++i)
                #pragma unroll
                for (int j = 0; j < 4; ++j)
                    wmma::mma_sync(acc[i][j], af[i], bf[j], acc[i][j]);
        }
        __syncthreads();
        buf ^= 1;
    }

    const float scale = (mode == 1) ? rsqrtf((float)kD) : 1.0f;
    #pragma unroll
    for (int i = 0; i < 2; ++i) {
        #pragma unroll
        for (int j = 0; j < 4; ++j) {
            if (mode == 1) {
                #pragma unroll
                for (int t = 0; t < acc[i][j].num_elements; ++t)
                    acc[i][j].x[t] *= scale;
            }
            const int mrow = m0 + wm + i * 16;
            const int ncol = n0 + wn + j * 16;
            float* dst;
            int ld;
            if (mode == 0) {
                dst = Cout + (size_t)mrow * N + ncol;
                ld  = N;
            } else {
                const int heads = (mode == 1) ? kHQ : kHK;
                const int b = mrow / kN, nseq = mrow % kN;
                const int h = ncol / kD, d = ncol % kD;
                dst = Cout + (((size_t)(b * heads + h) * kN + nseq) * kD + d);
                ld  = kD;
            }
            wmma::store_matrix_sync(dst, acc[i][j], ld, wmma::mem_row_major);
        }
    }
}

// ---------------------------------------------------------------------------
// Flash attention v2 (causal, GQA): BR=128 rows/CTA (8 warps x 16 rows),
// BC=64 KV tile, PTX mma m16n8k8 tf32, O in registers, cp.async KV pipeline.
// ---------------------------------------------------------------------------
#define BR  128
#define BC  64
#define ALD 132           // 128 + 4 pad (K/V/Q-stage row stride)
#define PLD 68            // 64 + 4 pad (P row stride)
#define KVSZ (BC * ALD)   // floats per KV buffer

// smem floats: K double + V double + P
#define ATTN_SMEM_FLOATS (4 * KVSZ + BR * PLD)
#define ATTN_SMEM_BYTES  (ATTN_SMEM_FLOATS * 4)

__global__ __launch_bounds__(256, 1) void attn_kernel(
    const float* __restrict__ Q, const float* __restrict__ K,
    const float* __restrict__ V, float* __restrict__ Ctx,
    const int* __restrict__ causal_flag)
{
    float* shK = dynsmem;                 // [2][KVSZ]
    float* shV = dynsmem + 2 * KVSZ;      // [2][KVSZ]
    unsigned* shP = (unsigned*)(dynsmem + 4 * KVSZ);   // [BR][PLD] tf32 bits

    const int t  = (gridDim.x - 1) - blockIdx.x;   // reversed: long CTAs first
    const int hq = blockIdx.y;
    const int b  = blockIdx.z;
    const int hk = hq >> 2;
    const int tid  = threadIdx.x;
    const int lane = tid & 31;
    const int w    = tid >> 5;
    const int q4   = lane & 3;          // thread-in-quad (col group)
    const int g4   = lane >> 2;         // quad id (row group)
    const bool causal = (*causal_flag) != 0;

    const float* Qb = Q + (((size_t)(b * kHQ + hq) * kN) + (size_t)t * BR) * kD;
    const float* Kb = K + ((size_t)(b * kHK + hk) * kN) * kD;
    const float* Vb = V + ((size_t)(b * kHK + hk) * kN) * kD;

    // ---- stage Q tile through shK region (2*KVSZ == BR*ALD exactly) ----
    #pragma unroll
    for (int i = 0; i < 16; ++i) {
        int f = tid + i * 256;            // 4096 float4
        int row = f >> 5, c4 = (f & 31) * 4;
        *(float4*)&shK[row * ALD + c4] = *(const float4*)(Qb + (size_t)row * kD + c4);
    }
    __syncthreads();

    // ---- extract Q A-fragments (persistent, tf32) ----
    const int r0 = w * 16 + g4;           // this thread's first row within CTA tile
    unsigned qa[16][4];
    #pragma unroll
    for (int ks = 0; ks < 16; ++ks) {
        qa[ks][0] = f2tf(shK[r0 * ALD + ks * 8 + q4]);
        qa[ks][1] = f2tf(shK[(r0 + 8) * ALD + ks * 8 + q4]);
        qa[ks][2] = f2tf(shK[r0 * ALD + ks * 8 + q4 + 4]);
        qa[ks][3] = f2tf(shK[(r0 + 8) * ALD + ks * 8 + q4 + 4]);
    }
    __syncthreads();   // done reading staged Q before cp.async overwrites shK

    float o[16][4];
    #pragma unroll
    for (int nt = 0; nt < 16; ++nt)
        #pragma unroll
        for (int e = 0; e < 4; ++e) o[nt][e] = 0.0f;
    float m0 = -1e30f, m1 = -1e30f, l0 = 0.0f, l1 = 0.0f;

    auto loadKV = [&](int bufi, int jt) {
        const float* Ks = Kb + (size_t)jt * BC * kD;
        const float* Vs = Vb + (size_t)jt * BC * kD;
        #pragma unroll
        for (int i = 0; i < 8; ++i) {
            int f = tid + i * 256;        // 2048 float4 per matrix
            int row = f >> 5, c4 = (f & 31) * 4;
            __pipeline_memcpy_async(&shK[bufi * KVSZ + row * ALD + c4],
                                    Ks + (size_t)row * kD + c4, 16);
            __pipeline_memcpy_async(&shV[bufi * KVSZ + row * ALD + c4],
                                    Vs + (size_t)row * kD + c4, 16);
        }
        __pipeline_commit();
    };

    const int jmax = causal ? (2 * t + 1) : (kN / BC - 1);
    const int qr0 = t * BR + r0;          // global query row (first)
    loadKV(0, 0);
    int buf = 0;

    for (int j = 0; j <= jmax; ++j) {
        const bool more = (j < jmax);
        if (more) loadKV(buf ^ 1, j + 1);
        __pipeline_wait_prior(more ? 1 : 0);
        __syncthreads();

        // warps whose 16 rows are entirely above the causal diagonal: skip
        const bool skipAll = causal && (j * BC > t * BR + w * 16 + 15);
        if (!skipAll) {
            const float* sK = shK + buf * KVSZ;
            const float* sV = shV + buf * KVSZ;

            // ---- S = Q @ K^T : 16 x 64, k=128 ----
            float s[8][4];
            #pragma unroll
            for (int nt = 0; nt < 8; ++nt)
                #pragma unroll
                for (int e = 0; e < 4; ++e) s[nt][e] = 0.0f;
            #pragma unroll
            for (int ks = 0; ks < 16; ++ks) {
                #pragma unroll
                for (int nt = 0; nt < 8; ++nt) {
                    unsigned b0 = f2tf(sK[(nt * 8 + g4) * ALD + ks * 8 + q4]);
                    unsigned b1 = f2tf(sK[(nt * 8 + g4) * ALD + ks * 8 + q4 + 4]);
                    mma_tf32(s[nt], qa[ks], b0, b1);
                }
            }

            // ---- causal mask (boundary tiles only) ----
            if (causal && j >= 2 * t) {
                #pragma unroll
                for (int nt = 0; nt < 8; ++nt) {
                    int c0 = j * BC + nt * 8 + 2 * q4;
                    if (c0 > qr0)         s[nt][0] = -1e30f;
                    if (c0 + 1 > qr0)     s[nt][1] = -1e30f;
                    if (c0 > qr0 + 8)     s[nt][2] = -1e30f;
                    if (c0 + 1 > qr0 + 8) s[nt][3] = -1e30f;
                }
            }

            // ---- online softmax in accumulator layout ----
            float ml0 = -1e30f, ml1 = -1e30f;
            #pragma unroll
            for (int nt = 0; nt < 8; ++nt) {
                ml0 = fmaxf(ml0, fmaxf(s[nt][0], s[nt][1]));
                ml1 = fmaxf(ml1, fmaxf(s[nt][2], s[nt][3]));
            }
            ml0 = fmaxf(ml0, __shfl_xor_sync(0xffffffffu, ml0, 1));
            ml0 = fmaxf(ml0, __shfl_xor_sync(0xffffffffu, ml0, 2));
            ml1 = fmaxf(ml1, __shfl_xor_sync(0xffffffffu, ml1, 1));
            ml1 = fmaxf(ml1, __shfl_xor_sync(0xffffffffu, ml1, 2));

            const float mn0 = fmaxf(m0, ml0), mn1 = fmaxf(m1, ml1);
            const float a0 = __expf(m0 - mn0), a1 = __expf(m1 - mn1);
            m0 = mn0; m1 = mn1;

            float ls0 = 0.0f, ls1 = 0.0f;
            #pragma unroll
            for (int nt = 0; nt < 8; ++nt) {
                float p0 = __expf(s[nt][0] - mn0);
                float p1 = __expf(s[nt][1] - mn0);
                float p2 = __expf(s[nt][2] - mn1);
                float p3 = __expf(s[nt][3] - mn1);
                ls0 += p0 + p1;
                ls1 += p2 + p3;
                unsigned* pr = shP + r0 * PLD + nt * 8 + 2 * q4;
                pr[0] = f2tf(p0);
                pr[1] = f2tf(p1);
                pr[8 * PLD]     = f2tf(p2);
                pr[8 * PLD + 1] = f2tf(p3);
            }
            ls0 += __shfl_xor_sync(0xffffffffu, ls0, 1);
            ls0 += __shfl_xor_sync(0xffffffffu, ls0, 2);
            ls1 += __shfl_xor_sync(0xffffffffu, ls1, 1);
            ls1 += __shfl_xor_sync(0xffffffffu, ls1, 2);
            l0 = a0 * l0 + ls0;
            l1 = a1 * l1 + ls1;

            // rescale O
            #pragma unroll
            for (int nt = 0; nt < 16; ++nt) {
                o[nt][0] *= a0; o[nt][1] *= a0;
                o[nt][2] *= a1; o[nt][3] *= a1;
            }

            // ---- O += P @ V : 16 x 128, k=64 (P rows are warp-private) ----
            #pragma unroll
            for (int ks = 0; ks < 8; ++ks) {
                unsigned pa[4];
                pa[0] = shP[r0 * PLD + ks * 8 + q4];
                pa[1] = shP[(r0 + 8) * PLD + ks * 8 + q4];
                pa[2] = shP[r0 * PLD + ks * 8 + q4 + 4];
                pa[3] = shP[(r0 + 8) * PLD + ks * 8 + q4 + 4];
                #pragma unroll
                for (int nt = 0; nt < 16; ++nt) {
                    unsigned b0 = f2tf(sV[(ks * 8 + q4) * ALD + nt * 8 + g4]);
                    unsigned b1 = f2tf(sV[(ks * 8 + q4 + 4) * ALD + nt * 8 + g4]);
                    mma_tf32(o[nt], pa, b0, b1);
                }
            }
        }
        __syncthreads();
        buf ^= 1;
    }

    // ---- epilogue: normalize, write Ctx[(b*N + row)][hq*D + d] ----
    const float inv0 = 1.0f / l0, inv1 = 1.0f / l1;
    const size_t base = ((size_t)b * kN + qr0) * kE + (size_t)hq * kD;
    #pragma unroll
    for (int nt = 0; nt < 16; ++nt) {
        float2 v0 = make_float2(o[nt][0] * inv0, o[nt][1] * inv0);
        float2 v1 = make_float2(o[nt][2] * inv1, o[nt][3] * inv1);
        *(float2*)&Ctx[base + nt * 8 + 2 * q4] = v0;
        *(float2*)&Ctx[base + (size_t)8 * kE + nt * 8 + 2 * q4] = v1;
    }
}

// ---------------------------------------------------------------------------
// Launch
// ---------------------------------------------------------------------------
extern "C" void kernel_launch(void* const* d_in, const int* in_sizes, int n_in,
                              void* d_out, int out_size)
{
    const float* query = (const float*)d_in[0];
    const float* key   = (const float*)d_in[1];
    const float* value = (const float*)d_in[2];
    const float* Wq    = (const float*)d_in[3];
    const float* bq    = (const float*)d_in[4];
    const float* Wk    = (const float*)d_in[5];
    const float* bk    = (const float*)d_in[6];
    const float* Wv    = (const float*)d_in[7];
    const float* bv    = (const float*)d_in[8];
    const float* Wo    = (const float*)d_in[9];
    const float* bo    = (const float*)d_in[10];
    const int* is_causal = (const int*)d_in[11];
    float* out = (float*)d_out;

    float *Qs, *Ks, *Vs, *Ctx;
    cudaGetSymbolAddress((void**)&Qs, g_Q);
    cudaGetSymbolAddress((void**)&Ks, g_K);
    cudaGetSymbolAddress((void**)&Vs, g_V);
    cudaGetSymbolAddress((void**)&Ctx, g_Ctx);

    const int gemmSmem = 2 * 2 * 128 * 36 * 4;   // 73728
    cudaFuncSetAttribute(gemm_xwt, cudaFuncAttributeMaxDynamicSharedMemorySize, gemmSmem);
    cudaFuncSetAttribute(attn_kernel, cudaFuncAttributeMaxDynamicSharedMemorySize,
                         ATTN_SMEM_BYTES);

    dim3 thr(256);
    gemm_xwt<<<dim3(kE / 128, kROWS / 128), thr, gemmSmem>>>(query, Wq, bq, Qs, kROWS, kE, kE, 1);
    gemm_xwt<<<dim3(kKVE / 128, kROWS / 128), thr, gemmSmem>>>(key, Wk, bk, Ks, kROWS, kKVE, kE, 2);
    gemm_xwt<<<dim3(kKVE / 128, kROWS / 128), thr, gemmSmem>>>(value, Wv, bv, Vs, kROWS, kKVE, kE, 2);
    attn_kernel<<<dim3(kN / BR, kHQ, kB), thr, ATTN_SMEM_BYTES>>>(Qs, Ks, Vs, Ctx, is_causal);
    gemm_xwt<<<dim3(kE / 128, kROWS / 128), thr, gemmSmem>>>(Ctx, Wo, bo, out, kROWS, kE, kE, 0);
}

// round 4
// speedup vs baseline: 5.1327x; 3.3654x over previous
#include <cuda_runtime.h>
#include <cuda_fp16.h>
#include <mma.h>
#include <cstdint>

using namespace nvcuda;

// Problem constants (fixed by the dataset)
#define kE    2048
#define kHQ   16
#define kHK   4
#define kD    128
#define kG    4
#define kKVE  512
#define kB    2
#define kN    2048
#define kROWS (kB * kN)
#define kK    2048

// ---------------------------------------------------------------------------
// Scratch (device globals — allocation-free per harness rules)
// ---------------------------------------------------------------------------
__device__ __align__(16) __half g_Qh[kB * kHQ * kN * kD];   // [b][hq][n][d] (pre-scaled)
__device__ __align__(16) __half g_Kh[kB * kHK * kN * kD];   // [b][hk][n][d]
__device__ __align__(16) __half g_Vth[kB * kHK * kD * kN];  // [b][hk][d][n]  (transposed!)
__device__ __align__(16) __half g_Ctxh[kB * kN * kE];       // [b*n][e]
// fp16 copies of inputs
__device__ __align__(16) __half g_q16[kROWS * kE];
__device__ __align__(16) __half g_k16[kROWS * kE];
__device__ __align__(16) __half g_v16[kROWS * kE];
__device__ __align__(16) __half g_Wq16[kE * kE];
__device__ __align__(16) __half g_Wk16[kKVE * kE];
__device__ __align__(16) __half g_Wv16[kKVE * kE];
__device__ __align__(16) __half g_Wo16[kE * kE];

extern __shared__ float dynsmem[];

__device__ __forceinline__ unsigned sm2u(const void* p) {
    unsigned a;
    asm("{ .reg .u64 t; cvta.to.shared.u64 t, %1; cvt.u32.u64 %0, t; }"
        : "=r"(a) : "l"(p));
    return a;
}
__device__ __forceinline__ void cpasync16(const void* dst_smem, const void* src) {
    asm volatile("cp.async.cg.shared.global [%0], [%1], 16;"
                 :: "r"(sm2u(dst_smem)), "l"(src) : "memory");
}
__device__ __forceinline__ void cpcommit() {
    asm volatile("cp.async.commit_group;" ::: "memory");
}
template <int N> __device__ __forceinline__ void cpwait() {
    asm volatile("cp.async.wait_group %0;" :: "n"(N) : "memory");
}
// fp16 MMA, fp32 accum
__device__ __forceinline__ void mma_f16(float* c, const unsigned* a,
                                        unsigned b0, unsigned b1) {
    asm volatile(
        "mma.sync.aligned.m16n8k16.row.col.f32.f16.f16.f32 "
        "{%0,%1,%2,%3}, {%4,%5,%6,%7}, {%8,%9}, {%0,%1,%2,%3};"
        : "+f"(c[0]), "+f"(c[1]), "+f"(c[2]), "+f"(c[3])
        : "r"(a[0]), "r"(a[1]), "r"(a[2]), "r"(a[3]), "r"(b0), "r"(b1));
}

// ---------------------------------------------------------------------------
// Prepass: fp32 -> fp16 conversion of all operand tensors
// ---------------------------------------------------------------------------
struct CJobs { const float* src[7]; __half* dst[7]; int n4[7]; };

__global__ __launch_bounds__(256) void conv_pass(CJobs j) {
    const int a = blockIdx.y;
    const float4* s = (const float4*)j.src[a];
    __half* d = j.dst[a];
    const int n = j.n4[a];
    for (int i = blockIdx.x * 256 + threadIdx.x; i < n; i += gridDim.x * 256) {
        float4 v = s[i];
        __half2 h0 = __floats2half2_rn(v.x, v.y);
        __half2 h1 = __floats2half2_rn(v.z, v.w);
        uint2 u;
        u.x = *(unsigned*)&h0;
        u.y = *(unsigned*)&h1;
        *(uint2*)(d + (size_t)i * 4) = u;
    }
}

// ---------------------------------------------------------------------------
// GEMM: C(128,128) = A @ W^T + bias.  fp16 wmma 16x16x16, BK=64, cp.async x2.
// mode 0: fp32 row-major out
// mode 1: Q scatter  (half, *1/sqrt(D)) -> [b][hq][n][d]
// mode 2: K scatter  (half)             -> [b][hk][n][d]
// mode 3: V^T scatter(half)             -> [b][hk][d][n]
// ---------------------------------------------------------------------------
#define BKh 64
#define LDW 72     // BK + 8 pad, halves
#define LDE 132    // epilogue f32 staging stride
#define GEMM_SMEM_BYTES 73728   // 2 buf * 2 mat * 128*72*2B

__device__ void gemm_tile_f16(const __half* __restrict__ A, const __half* __restrict__ W,
                              const float* __restrict__ bias, void* __restrict__ Cout,
                              int Nfull, int mt, int nt, int mode)
{
    __half* shA = (__half*)dynsmem;                 // [2][128*LDW]
    __half* shB = shA + 2 * 128 * LDW;              // [2][128*LDW]

    const int tid = threadIdx.x;
    const int w = tid >> 5;
    const int m0 = mt * 128, n0 = nt * 128;
    const int wm = (w & 3) * 32;
    const int wn = (w >> 2) * 64;

    wmma::fragment<wmma::accumulator, 16, 16, 16, float> acc[2][4];
    #pragma unroll
    for (int i = 0; i < 2; ++i)
        #pragma unroll
        for (int j = 0; j < 4; ++j)
            wmma::load_matrix_sync(acc[i][j], bias + n0 + wn + j * 16, 0, wmma::mem_row_major);

    auto stage = [&](int bufi, int k0) {
        __half* dA = shA + bufi * 128 * LDW;
        __half* dB = shB + bufi * 128 * LDW;
        #pragma unroll
        for (int i = 0; i < 4; ++i) {
            int g = tid + i * 256;                  // 1024 16B-chunks per matrix
            int row = g >> 3, seg = (g & 7) * 8;
            cpasync16(dA + row * LDW + seg, A + (size_t)(m0 + row) * kK + k0 + seg);
            cpasync16(dB + row * LDW + seg, W + (size_t)(n0 + row) * kK + k0 + seg);
        }
        cpcommit();
    };

    stage(0, 0);
    int buf = 0;
    for (int k0 = 0; k0 < kK; k0 += BKh) {
        const bool more = (k0 + BKh < kK);
        if (more) stage(buf ^ 1, k0 + BKh);
        if (more) cpwait<1>(); else cpwait<0>();
        __syncthreads();

        const __half* sA = shA + buf * 128 * LDW;
        const __half* sB = shB + buf * 128 * LDW;
        #pragma unroll
        for (int kk = 0; kk < BKh; kk += 16) {
            wmma::fragment<wmma::matrix_a, 16, 16, 16, __half, wmma::row_major> af[2];
            wmma::fragment<wmma::matrix_b, 16, 16, 16, __half, wmma::col_major> bf[4];
            #pragma unroll
            for (int i = 0; i < 2; ++i)
                wmma::load_matrix_sync(af[i], sA + (wm + i * 16) * LDW + kk, LDW);
            #pragma unroll
            for (int j = 0; j < 4; ++j)
                wmma::load_matrix_sync(bf[j], sB + (wn + j * 16) * LDW + kk, LDW);
            #pragma unroll
            for (int i = 0; i < 2; ++i)
                #pragma unroll
                for (int j = 0; j < 4; ++j)
                    wmma::mma_sync(acc[i][j], af[i], bf[j], acc[i][j]);
        }
        __syncthreads();
        buf ^= 1;
    }

    // ---- epilogue: stage f32 tile in smem, then scatter ----
    float* eb = dynsmem;   // 128 x LDE f32 (67584 B <= 73728)
    #pragma unroll
    for (int i = 0; i < 2; ++i)
        #pragma unroll
        for (int j = 0; j < 4; ++j)
            wmma::store_matrix_sync(eb + (wm + i * 16) * LDE + wn + j * 16,
                                    acc[i][j], LDE, wmma::mem_row_major);
    __syncthreads();

    if (mode == 0) {
        float* out = (float*)Cout;
        for (int idx = tid; idx < 128 * 128; idx += 256) {
            int m = idx >> 7, c = idx & 127;
            out[(size_t)(m0 + m) * Nfull + n0 + c] = eb[m * LDE + c] + bias[n0 + c];
        }
    } else if (mode == 3) {
        __half* out = (__half*)Cout;
        for (int idx = tid; idx < 128 * 128; idx += 256) {
            int c = idx >> 7, m = idx & 127;       // c = d col, m = token
            int n = n0 + c;
            int h = n >> 7, d = n & 127;
            int token = m0 + m;
            int bb = token >> 11, ns = token & (kN - 1);
            out[((size_t)(bb * kHK + h) * kD + d) * kN + ns] =
                __float2half_rn(eb[m * LDE + c] + bias[n]);
        }
    } else {
        __half* out = (__half*)Cout;
        const int H = (mode == 1) ? kHQ : kHK;
        const float scale = (mode == 1) ? 0.08838834764831845f : 1.0f;
        for (int idx = tid; idx < 128 * 128; idx += 256) {
            int m = idx >> 7, c = idx & 127;
            int n = n0 + c;
            int h = n >> 7, d = n & 127;
            int token = m0 + m;
            int bb = token >> 11, ns = token & (kN - 1);
            out[((size_t)(bb * H + h) * kN + ns) * kD + d] =
                __float2half_rn((eb[m * LDE + c] + bias[n]) * scale);
        }
    }
}

// Fused Q/K/V projections
__global__ __launch_bounds__(256, 1) void qkv_gemm(
    const __half* __restrict__ Aq, const __half* __restrict__ Ak, const __half* __restrict__ Av,
    const __half* __restrict__ Wq, const __half* __restrict__ Wk, const __half* __restrict__ Wv,
    const float* __restrict__ bq, const float* __restrict__ bk, const float* __restrict__ bv,
    __half* __restrict__ Qo, __half* __restrict__ Ko, __half* __restrict__ Vo)
{
    const int job = blockIdx.x;
    if (job < 512)
        gemm_tile_f16(Aq, Wq, bq, Qo, kE, job >> 4, job & 15, 1);
    else if (job < 640)
        gemm_tile_f16(Ak, Wk, bk, Ko, kKVE, (job - 512) >> 2, (job - 512) & 3, 2);
    else
        gemm_tile_f16(Av, Wv, bv, Vo, kKVE, (job - 640) >> 2, (job - 640) & 3, 3);
}

__global__ __launch_bounds__(256, 1) void o_gemm(
    const __half* __restrict__ A, const __half* __restrict__ W,
    const float* __restrict__ bias, float* __restrict__ Cout)
{
    gemm_tile_f16(A, W, bias, Cout, kE, blockIdx.x >> 4, blockIdx.x & 15, 0);
}

// ---------------------------------------------------------------------------
// Flash attention fp16: BR=128 (8 warps x 16 rows), BC=64, m16n8k16 MMA,
// O in fp32 registers, cp.async KV pipeline, V pre-transposed.
// ---------------------------------------------------------------------------
#define BR  128
#define BC  64
#define LDK 136    // 128 + 8 halves (K tile rows: d)
#define LDV 72     // 64 + 8 halves  (V^T tile rows: d, cols: kv)
#define LDP 72     // 64 + 8 halves
#define KSZ (BC * LDK)   // halves per K buffer
#define VSZ (128 * LDV)  // halves per V buffer
// halves: K double + V double + P
#define ATTN_SMEM_HALVES (2 * KSZ + 2 * VSZ + BR * LDP)
#define ATTN_SMEM_BYTES  (ATTN_SMEM_HALVES * 2)

__global__ __launch_bounds__(256, 1) void attn_kernel(
    const __half* __restrict__ Q, const __half* __restrict__ K,
    const __half* __restrict__ Vt, __half* __restrict__ Ctx,
    const int* __restrict__ causal_flag)
{
    __half* hs  = (__half*)dynsmem;
    __half* shK = hs;                    // [2][KSZ]
    __half* shV = hs + 2 * KSZ;          // [2][VSZ]
    __half* shP = hs + 2 * KSZ + 2 * VSZ;

    const int t  = (gridDim.x - 1) - blockIdx.x;
    const int hq = blockIdx.y;
    const int b  = blockIdx.z;
    const int hk = hq >> 2;
    const int tid  = threadIdx.x;
    const int lane = tid & 31;
    const int w    = tid >> 5;
    const int q4   = lane & 3;
    const int g4   = lane >> 2;
    const bool causal = (*causal_flag) != 0;

    const __half* Qb = Q + (((size_t)(b * kHQ + hq) * kN) + (size_t)t * BR) * kD;
    const __half* Kb = K + ((size_t)(b * kHK + hk) * kN) * kD;
    const __half* Vb = Vt + ((size_t)(b * kHK + hk) * kD) * kN;

    // ---- stage Q tile (128 x 128 halves) into shK region (2*KSZ >= 128*LDK) ----
    #pragma unroll
    for (int i = 0; i < 8; ++i) {
        int f = tid + i * 256;               // 2048 16B chunks
        int row = f >> 4, seg = (f & 15) * 8;
        *(uint4*)&shK[row * LDK + seg] = *(const uint4*)(Qb + (size_t)row * kD + seg);
    }
    __syncthreads();

    // ---- extract persistent Q A-fragments (m16n8k16, 8 k-steps) ----
    const int r0 = w * 16 + g4;
    unsigned qa[8][4];
    #pragma unroll
    for (int ks = 0; ks < 8; ++ks) {
        qa[ks][0] = *(const unsigned*)&shK[r0 * LDK + ks * 16 + 2 * q4];
        qa[ks][1] = *(const unsigned*)&shK[(r0 + 8) * LDK + ks * 16 + 2 * q4];
        qa[ks][2] = *(const unsigned*)&shK[r0 * LDK + ks * 16 + 2 * q4 + 8];
        qa[ks][3] = *(const unsigned*)&shK[(r0 + 8) * LDK + ks * 16 + 2 * q4 + 8];
    }
    __syncthreads();

    float o[16][4];
    #pragma unroll
    for (int nt = 0; nt < 16; ++nt)
        #pragma unroll
        for (int e = 0; e < 4; ++e) o[nt][e] = 0.0f;
    float m0 = -1e30f, m1 = -1e30f, l0 = 0.0f, l1 = 0.0f;

    auto loadKV = [&](int bufi, int jt) {
        const __half* Ks = Kb + (size_t)jt * BC * kD;
        const __half* Vs = Vb + (size_t)jt * BC;
        __half* dK = shK + bufi * KSZ;
        __half* dV = shV + bufi * VSZ;
        #pragma unroll
        for (int i = 0; i < 4; ++i) {
            int f = tid + i * 256;               // K: 1024 chunks (64 rows x 16)
            int row = f >> 4, seg = (f & 15) * 8;
            cpasync16(dK + row * LDK + seg, Ks + (size_t)row * kD + seg);
        }
        #pragma unroll
        for (int i = 0; i < 4; ++i) {
            int f = tid + i * 256;               // V^T: 1024 chunks (128 rows x 8)
            int row = f >> 3, seg = (f & 7) * 8;
            cpasync16(dV + row * LDV + seg, Vs + (size_t)row * kN + seg);
        }
        cpcommit();
    };

    const int jmax = causal ? (2 * t + 1) : (kN / BC - 1);
    const int qr0 = t * BR + r0;
    loadKV(0, 0);
    int buf = 0;

    for (int j = 0; j <= jmax; ++j) {
        const bool more = (j < jmax);
        if (more) loadKV(buf ^ 1, j + 1);
        if (more) cpwait<1>(); else cpwait<0>();
        __syncthreads();

        const bool skipAll = causal && (j * BC > t * BR + w * 16 + 15);
        if (!skipAll) {
            const __half* sK = shK + buf * KSZ;
            const __half* sV = shV + buf * VSZ;

            // ---- S = Q @ K^T : 16 x 64, k=128 (8 k-steps) ----
            float s[8][4];
            #pragma unroll
            for (int nt = 0; nt < 8; ++nt)
                #pragma unroll
                for (int e = 0; e < 4; ++e) s[nt][e] = 0.0f;
            #pragma unroll
            for (int ks = 0; ks < 8; ++ks) {
                #pragma unroll
                for (int nt = 0; nt < 8; ++nt) {
                    const __half* kr = sK + (nt * 8 + g4) * LDK + ks * 16 + 2 * q4;
                    unsigned b0 = *(const unsigned*)kr;
                    unsigned b1 = *(const unsigned*)(kr + 8);
                    mma_f16(s[nt], qa[ks], b0, b1);
                }
            }

            if (causal && j >= 2 * t) {
                #pragma unroll
                for (int nt = 0; nt < 8; ++nt) {
                    int c0 = j * BC + nt * 8 + 2 * q4;
                    if (c0 > qr0)         s[nt][0] = -1e30f;
                    if (c0 + 1 > qr0)     s[nt][1] = -1e30f;
                    if (c0 > qr0 + 8)     s[nt][2] = -1e30f;
                    if (c0 + 1 > qr0 + 8) s[nt][3] = -1e30f;
                }
            }

            float ml0 = -1e30f, ml1 = -1e30f;
            #pragma unroll
            for (int nt = 0; nt < 8; ++nt) {
                ml0 = fmaxf(ml0, fmaxf(s[nt][0], s[nt][1]));
                ml1 = fmaxf(ml1, fmaxf(s[nt][2], s[nt][3]));
            }
            ml0 = fmaxf(ml0, __shfl_xor_sync(0xffffffffu, ml0, 1));
            ml0 = fmaxf(ml0, __shfl_xor_sync(0xffffffffu, ml0, 2));
            ml1 = fmaxf(ml1, __shfl_xor_sync(0xffffffffu, ml1, 1));
            ml1 = fmaxf(ml1, __shfl_xor_sync(0xffffffffu, ml1, 2));

            const float mn0 = fmaxf(m0, ml0), mn1 = fmaxf(m1, ml1);
            const float a0 = __expf(m0 - mn0), a1 = __expf(m1 - mn1);
            m0 = mn0; m1 = mn1;

            float ls0 = 0.0f, ls1 = 0.0f;
            #pragma unroll
            for (int nt = 0; nt < 8; ++nt) {
                float p0 = __expf(s[nt][0] - mn0);
                float p1 = __expf(s[nt][1] - mn0);
                float p2 = __expf(s[nt][2] - mn1);
                float p3 = __expf(s[nt][3] - mn1);
                ls0 += p0 + p1;
                ls1 += p2 + p3;
                __half2 hp0 = __floats2half2_rn(p0, p1);
                __half2 hp1 = __floats2half2_rn(p2, p3);
                *(__half2*)&shP[r0 * LDP + nt * 8 + 2 * q4] = hp0;
                *(__half2*)&shP[(r0 + 8) * LDP + nt * 8 + 2 * q4] = hp1;
            }
            ls0 += __shfl_xor_sync(0xffffffffu, ls0, 1);
            ls0 += __shfl_xor_sync(0xffffffffu, ls0, 2);
            ls1 += __shfl_xor_sync(0xffffffffu, ls1, 1);
            ls1 += __shfl_xor_sync(0xffffffffu, ls1, 2);
            l0 = a0 * l0 + ls0;
            l1 = a1 * l1 + ls1;

            #pragma unroll
            for (int nt = 0; nt < 16; ++nt) {
                o[nt][0] *= a0; o[nt][1] *= a0;
                o[nt][2] *= a1; o[nt][3] *= a1;
            }

            // ---- O += P @ V : 16 x 128, k=64 (4 k-steps) ----
            #pragma unroll
            for (int ks = 0; ks < 4; ++ks) {
                unsigned pa[4];
                pa[0] = *(const unsigned*)&shP[r0 * LDP + ks * 16 + 2 * q4];
                pa[1] = *(const unsigned*)&shP[(r0 + 8) * LDP + ks * 16 + 2 * q4];
                pa[2] = *(const unsigned*)&shP[r0 * LDP + ks * 16 + 2 * q4 + 8];
                pa[3] = *(const unsigned*)&shP[(r0 + 8) * LDP + ks * 16 + 2 * q4 + 8];
                #pragma unroll
                for (int nt = 0; nt < 16; ++nt) {
                    const __half* vr = sV + (nt * 8 + g4) * LDV + ks * 16 + 2 * q4;
                    unsigned b0 = *(const unsigned*)vr;
                    unsigned b1 = *(const unsigned*)(vr + 8);
                    mma_f16(o[nt], pa, b0, b1);
                }
            }
        }
        __syncthreads();
        buf ^= 1;
    }

    // ---- epilogue: normalize, write Ctx (half) ----
    const float inv0 = 1.0f / l0, inv1 = 1.0f / l1;
    const size_t base = ((size_t)b * kN + qr0) * kE + (size_t)hq * kD;
    #pragma unroll
    for (int nt = 0; nt < 16; ++nt) {
        __half2 v0 = __floats2half2_rn(o[nt][0] * inv0, o[nt][1] * inv0);
        __half2 v1 = __floats2half2_rn(o[nt][2] * inv1, o[nt][3] * inv1);
        *(__half2*)&Ctx[base + nt * 8 + 2 * q4] = v0;
        *(__half2*)&Ctx[base + (size_t)8 * kE + nt * 8 + 2 * q4] = v1;
    }
}

// ---------------------------------------------------------------------------
// Launch
// ---------------------------------------------------------------------------
extern "C" void kernel_launch(void* const* d_in, const int* in_sizes, int n_in,
                              void* d_out, int out_size)
{
    const float* query = (const float*)d_in[0];
    const float* key   = (const float*)d_in[1];
    const float* value = (const float*)d_in[2];
    const float* Wq    = (const float*)d_in[3];
    const float* bq    = (const float*)d_in[4];
    const float* Wk    = (const float*)d_in[5];
    const float* bk    = (const float*)d_in[6];
    const float* Wv    = (const float*)d_in[7];
    const float* bv    = (const float*)d_in[8];
    const float* Wo    = (const float*)d_in[9];
    const float* bo    = (const float*)d_in[10];
    const int* is_causal = (const int*)d_in[11];
    float* out = (float*)d_out;

    __half *Qh, *Kh, *Vth, *Ctxh, *q16, *k16, *v16, *Wq16, *Wk16, *Wv16, *Wo16;
    cudaGetSymbolAddress((void**)&Qh, g_Qh);
    cudaGetSymbolAddress((void**)&Kh, g_Kh);
    cudaGetSymbolAddress((void**)&Vth, g_Vth);
    cudaGetSymbolAddress((void**)&Ctxh, g_Ctxh);
    cudaGetSymbolAddress((void**)&q16, g_q16);
    cudaGetSymbolAddress((void**)&k16, g_k16);
    cudaGetSymbolAddress((void**)&v16, g_v16);
    cudaGetSymbolAddress((void**)&Wq16, g_Wq16);
    cudaGetSymbolAddress((void**)&Wk16, g_Wk16);
    cudaGetSymbolAddress((void**)&Wv16, g_Wv16);
    cudaGetSymbolAddress((void**)&Wo16, g_Wo16);

    cudaFuncSetAttribute(qkv_gemm, cudaFuncAttributeMaxDynamicSharedMemorySize, GEMM_SMEM_BYTES);
    cudaFuncSetAttribute(o_gemm,  cudaFuncAttributeMaxDynamicSharedMemorySize, GEMM_SMEM_BYTES);
    cudaFuncSetAttribute(attn_kernel, cudaFuncAttributeMaxDynamicSharedMemorySize, ATTN_SMEM_BYTES);

    CJobs cj;
    cj.src[0] = query; cj.dst[0] = q16;  cj.n4[0] = kROWS * kE / 4;
    cj.src[1] = key;   cj.dst[1] = k16;  cj.n4[1] = kROWS * kE / 4;
    cj.src[2] = value; cj.dst[2] = v16;  cj.n4[2] = kROWS * kE / 4;
    cj.src[3] = Wq;    cj.dst[3] = Wq16; cj.n4[3] = kE * kE / 4;
    cj.src[4] = Wk;    cj.dst[4] = Wk16; cj.n4[4] = kKVE * kE / 4;
    cj.src[5] = Wv;    cj.dst[5] = Wv16; cj.n4[5] = kKVE * kE / 4;
    cj.src[6] = Wo;    cj.dst[6] = Wo16; cj.n4[6] = kE * kE / 4;

    conv_pass<<<dim3(512, 7), 256>>>(cj);
    qkv_gemm<<<768, 256, GEMM_SMEM_BYTES>>>(q16, k16, v16, Wq16, Wk16, Wv16,
                                            bq, bk, bv, Qh, Kh, Vth);
    attn_kernel<<<dim3(kN / BR, kHQ, kB), 256, ATTN_SMEM_BYTES>>>(Qh, Kh, Vth, Ctxh, is_causal);
    o_gemm<<<512, 256, GEMM_SMEM_BYTES>>>(Ctxh, Wo16, bo, out);
}